// round 7
// baseline (speedup 1.0000x reference)
#include <cuda_runtime.h>

#define NB 256
#define NT 1024
#define ND0 32
#define NH 64
#define NM (NB * NT)

__device__ float g_gx0[(size_t)NM * 256];   // L0 gate pre-activations (transposed: [tok][l*4+gate])
__device__ float4 g_wblob[16][256];         // L1 gates (g,o) weights, chunk-major, shared by all CTAs

using ull = unsigned long long;

__device__ __forceinline__ void ffma2(ull& d, ull a, ull b) {
    asm("fma.rn.f32x2 %0, %1, %2, %0;" : "+l"(d) : "l"(a), "l"(b));
}
__device__ __forceinline__ ull packf2(float x, float y) {
    ull r; asm("mov.b64 %0, {%1, %2};" : "=l"(r) : "f"(x), "f"(y)); return r;
}
__device__ __forceinline__ float2 unpackf2(ull v) {
    float2 f; asm("mov.b64 {%0, %1}, %2;" : "=f"(f.x), "=f"(f.y) : "l"(v)); return f;
}
__device__ __forceinline__ float ftanh(float x) {
    float y; asm("tanh.approx.f32 %0, %1;" : "=f"(y) : "f"(x)); return y;
}
__device__ __forceinline__ float fsig(float x) {
    return fmaf(0.5f, ftanh(0.5f * x), 0.5f);
}
__device__ __forceinline__ void cp_async16(void* s, const void* g) {
    unsigned sa = (unsigned)__cvta_generic_to_shared(s);
    asm volatile("cp.async.cg.shared.global [%0], [%1], 16;" :: "r"(sa), "l"(g));
}

// ===================== layer-0 gate GEMM (parallel) =====================
// Stores TRANSPOSED per-token gate layout: gx[tok][l*4 + gatetype] so the
// recurrence cell reads all 4 gates of lane l with one LDS.128.
template <int K>
__global__ __launch_bounds__(256) void gate_gemm(
    const float* __restrict__ X,     // [M][K]
    const float* __restrict__ w_ih,  // [256][K]
    const float* __restrict__ b_ih,
    const float* __restrict__ b_hh,
    float* __restrict__ gx)          // [M][256] transposed layout
{
    constexpr int TP = 68;
    __shared__ __align__(16) float xT[K][TP];

    const int g = threadIdx.x;
    const size_t tok0 = (size_t)blockIdx.x * 64;

#pragma unroll
    for (int j = 0; j < K / 16; j++) {
        const int idx4 = threadIdx.x + j * 256;
        const int tau  = idx4 / (K / 4);
        const int kc   = idx4 - tau * (K / 4);
        const float4 v = reinterpret_cast<const float4*>(X + (tok0 + tau) * K)[kc];
        xT[4 * kc + 0][tau] = v.x;
        xT[4 * kc + 1][tau] = v.y;
        xT[4 * kc + 2][tau] = v.z;
        xT[4 * kc + 3][tau] = v.w;
    }

    float w[K];
#pragma unroll
    for (int k = 0; k < K; k++) w[k] = w_ih[g * K + k];

    const float bias = b_ih[g] + b_hh[g];
    ull acc[32];
    const ull bp = packf2(bias, bias);
#pragma unroll
    for (int i = 0; i < 32; i++) acc[i] = bp;

    __syncthreads();

#pragma unroll 4
    for (int k = 0; k < K; k++) {
        const ull wb = packf2(w[k], w[k]);
        const ulonglong2* row = reinterpret_cast<const ulonglong2*>(&xT[k][0]);
#pragma unroll
        for (int i = 0; i < 16; i++) {
            const ulonglong2 v = row[i];
            ffma2(acc[2 * i],     v.x, wb);
            ffma2(acc[2 * i + 1], v.y, wb);
        }
    }

    const int col = (g & 63) * 4 + (g >> 6);   // transposed column
#pragma unroll
    for (int p = 0; p < 32; p++) {
        const float2 f = unpackf2(acc[p]);
        gx[(tok0 + 2 * p) * 256 + col]     = f.x;
        gx[(tok0 + 2 * p + 1) * 256 + col] = f.y;
    }
}

// ===================== weight blob packer (one tiny block) =====================
// Blob holds L1 gates g4=2 (g) and g4=3 (o): chunk c in [0,16): g4 = 2+(c>>3),
// float4 covers kk = 32*k1 + 4*(c&7) .. +3 of thread rt=(l1<<2)|k1.
__global__ void pack_w1(const float* __restrict__ w_ih1,
                        const float* __restrict__ w_hh1)
{
    const int rt = threadIdx.x;          // 0..255
    const int k1 = rt & 3, l1 = rt >> 2;
#pragma unroll
    for (int c = 0; c < 16; c++) {
        const int g4 = 2 + (c >> 3), i2 = c & 7;
        const int row = 64 * g4 + l1;
        float4 v;
        float* vp = reinterpret_cast<float*>(&v);
#pragma unroll
        for (int e = 0; e < 4; e++) {
            const int kk = 32 * k1 + 4 * i2 + e;
            vp[e] = (kk < 64) ? w_ih1[row * 64 + kk] : w_hh1[row * 64 + kk - 64];
        }
        g_wblob[c][rt] = v;
    }
}

// ===================== fused L0 + L1 recurrence, 512 threads =====================
// 2 samples/CTA, grid 128 (1 CTA/SM), 16 warps.
//  L0 (tid<256): (l0=tid>>2, p0=(tid>>1)&1, k0=tid&1): 2 gates (p0=0:(i,g),
//     p0=1:(f,o)) x K/2 x both samples; xor(1) k-reduce, xor(2) gate exchange;
//     cells on p0==0 (sample=k0). gx0 via cp.async ring, read as 1 LDS.128.
//  L1 (tid>=256): (l1=rt>>2, k1=rt&3): 4 gates x K/4 x both samples; gates i,f
//     in regs, gates g,o streamed from g_wblob (L1$-resident, coalesced);
//     xor(1)+xor(2) reduce; cells on k1<2 (sample=k1). Lag-1 vs L0.
__global__ __launch_bounds__(512) void lstm_fused(
    const float* __restrict__ gx0,
    const float* __restrict__ w_hh0,  // [256][64]
    const float* __restrict__ w_ih1,  // [256][64]
    const float* __restrict__ w_hh1,  // [256][64]
    const float* __restrict__ b_ih1,
    const float* __restrict__ b_hh1,
    const float* __restrict__ w_fc,
    const float* __restrict__ b_fc,
    float* __restrict__ out)
{
    constexpr int PF = 7;

    __shared__ __align__(16) float ubuf[2][2][2][68];  // [buf][sample][h1/h2][64+pad]
    __shared__ __align__(16) float gxs[8][2][256];
    __shared__ float red[2][NH];

    const int tid = threadIdx.x;
    const int b0  = blockIdx.x * 2;
    const bool isL0 = (tid < 256);

    for (int i = tid; i < 2 * 2 * 2 * 68; i += 512)
        (&ubuf[0][0][0][0])[i] = 0.0f;

    // ids
    const int k0 = tid & 1, p0 = (tid >> 1) & 1, l0 = tid >> 2;   // L0 (l0<64 valid)
    const int rt = tid - 256;
    const int k1 = rt & 3, l1 = rt >> 2;                          // L1

    ull w0[2][16];      // L0: 2 gate rows x 32 floats
    ull w1[2][16];      // L1: gates i,f x 32 floats
    float bi = 0.f, bf_ = 0.f, bg = 0.f, bo = 0.f;

    if (isL0) {
        const int r0 = (p0 ? 64 : 0) + l0;        // i or f
        const int r1 = (p0 ? 192 : 128) + l0;     // g or o
#pragma unroll
        for (int i = 0; i < 16; i++) {
            const int k = 32 * k0 + 2 * i;
            w0[0][i] = packf2(w_hh0[r0 * NH + k], w_hh0[r0 * NH + k + 1]);
            w0[1][i] = packf2(w_hh0[r1 * NH + k], w_hh0[r1 * NH + k + 1]);
        }
    } else {
#pragma unroll
        for (int g4 = 0; g4 < 2; g4++) {
            const int row = 64 * g4 + l1;
#pragma unroll
            for (int i = 0; i < 16; i++) {
                const int kk = 32 * k1 + 2 * i;
                const float a = (kk < 64) ? w_ih1[row * 64 + kk]
                                          : w_hh1[row * 64 + kk - 64];
                const float b = (kk + 1 < 64) ? w_ih1[row * 64 + kk + 1]
                                              : w_hh1[row * 64 + kk - 63];
                w1[g4][i] = packf2(a, b);
            }
        }
        bi  = b_ih1[l1]       + b_hh1[l1];
        bf_ = b_ih1[64 + l1]  + b_hh1[64 + l1];
        bg  = b_ih1[128 + l1] + b_hh1[128 + l1];
        bo  = b_ih1[192 + l1] + b_hh1[192 + l1];
    }

    // gx0 ring loaders: tid<128
    const int ls = tid >> 6, li = tid & 63;
    const float* gsrc = gx0 + ((size_t)(b0 + ls) * NT) * 256 + li * 4;
    if (tid < 128) {
#pragma unroll
        for (int p = 0; p < PF; p++) {
            cp_async16(&gxs[p][ls][li * 4], gsrc + (size_t)p * 256);
            asm volatile("cp.async.commit_group;");
        }
        asm volatile("cp.async.wait_group %0;" :: "n"(PF - 1));
    }
    __syncthreads();

    float c_st = 0.f, h_last = 0.f;
    const float4* wb = &g_wblob[0][0];

#pragma unroll 1
    for (int t = 0; t <= NT; t++) {
        const int cb = t & 1, nb_ = (t + 1) & 1;

        if (isL0) {
            if (t < NT) {
                const ulonglong2* uA =
                    reinterpret_cast<const ulonglong2*>(&ubuf[cb][0][0][k0 * 32]);
                const ulonglong2* uB =
                    reinterpret_cast<const ulonglong2*>(&ubuf[cb][1][0][k0 * 32]);
                ull A00 = 0, A10 = 0, A01 = 0, A11 = 0;   // [gate][sample]
#pragma unroll
                for (int i = 0; i < 8; i++) {
                    const ulonglong2 va = uA[i];
                    const ulonglong2 vb = uB[i];
                    ffma2(A00, va.x, w0[0][2 * i]); ffma2(A00, va.y, w0[0][2 * i + 1]);
                    ffma2(A10, va.x, w0[1][2 * i]); ffma2(A10, va.y, w0[1][2 * i + 1]);
                    ffma2(A01, vb.x, w0[0][2 * i]); ffma2(A01, vb.y, w0[0][2 * i + 1]);
                    ffma2(A11, vb.x, w0[1][2 * i]); ffma2(A11, vb.y, w0[1][2 * i + 1]);
                }
                float2 f;
                float S0[2], S1[2];
                f = unpackf2(A00); S0[0] = f.x + f.y;
                f = unpackf2(A01); S0[1] = f.x + f.y;
                f = unpackf2(A10); S1[0] = f.x + f.y;
                f = unpackf2(A11); S1[1] = f.x + f.y;
#pragma unroll
                for (int s = 0; s < 2; s++) {
                    S0[s] += __shfl_xor_sync(0xffffffffu, S0[s], 1);
                    S1[s] += __shfl_xor_sync(0xffffffffu, S1[s], 1);
                }
                // exchange with p-partner (xor 2); my cell sample = k0
                const float own0 = S0[k0], own1 = S1[k0];
                const float rx0 = __shfl_xor_sync(0xffffffffu, own0, 2);  // f (for p0=0)
                const float rx1 = __shfl_xor_sync(0xffffffffu, own1, 2);  // o
                if (p0 == 0) {
                    const float4 gq =
                        *reinterpret_cast<const float4*>(&gxs[t & 7][k0][l0 * 4]);
                    const float gi = S0[k0] + gq.x;   // i
                    const float gf = rx0    + gq.y;   // f
                    const float gg = S1[k0] + gq.z;   // g
                    const float go = rx1    + gq.w;   // o
                    c_st = fsig(gf) * c_st + fsig(gi) * ftanh(gg);
                    ubuf[nb_][k0][0][l0] = fsig(go) * ftanh(c_st);
                }
            }
            if (tid < 128) {
                if (t + PF < NT)
                    cp_async16(&gxs[(t + PF) & 7][ls][li * 4],
                               gsrc + (size_t)(t + PF) * 256);
                asm volatile("cp.async.commit_group;");
                asm volatile("cp.async.wait_group %0;" :: "n"(PF - 1));
            }
        } else {
            // L1 (lag 1): h2[t-1] from [h1(t-1); h2(t-2)]
            const ulonglong2* uA = reinterpret_cast<const ulonglong2*>(
                &ubuf[cb][0][k1 >> 1][(k1 & 1) * 32]);
            const ulonglong2* uB = reinterpret_cast<const ulonglong2*>(
                &ubuf[cb][1][k1 >> 1][(k1 & 1) * 32]);
            ull A[4][2];
#pragma unroll
            for (int g4 = 0; g4 < 4; g4++) { A[g4][0] = 0; A[g4][1] = 0; }

            float4 c2 = wb[0 * 256 + rt];
            float4 c3 = wb[8 * 256 + rt];
#pragma unroll
            for (int i = 0; i < 8; i++) {
                float4 n2, n3;
                if (i < 7) {
                    n2 = wb[(i + 1) * 256 + rt];
                    n3 = wb[(i + 9) * 256 + rt];
                }
                const ulonglong2 va = uA[i];
                const ulonglong2 vb = uB[i];
                // reg gates i,f
                ffma2(A[0][0], va.x, w1[0][2 * i]); ffma2(A[0][0], va.y, w1[0][2 * i + 1]);
                ffma2(A[1][0], va.x, w1[1][2 * i]); ffma2(A[1][0], va.y, w1[1][2 * i + 1]);
                ffma2(A[0][1], vb.x, w1[0][2 * i]); ffma2(A[0][1], vb.y, w1[0][2 * i + 1]);
                ffma2(A[1][1], vb.x, w1[1][2 * i]); ffma2(A[1][1], vb.y, w1[1][2 * i + 1]);
                // blob gates g,o
                const ull c2lo = reinterpret_cast<const ull*>(&c2)[0];
                const ull c2hi = reinterpret_cast<const ull*>(&c2)[1];
                const ull c3lo = reinterpret_cast<const ull*>(&c3)[0];
                const ull c3hi = reinterpret_cast<const ull*>(&c3)[1];
                ffma2(A[2][0], va.x, c2lo); ffma2(A[2][0], va.y, c2hi);
                ffma2(A[3][0], va.x, c3lo); ffma2(A[3][0], va.y, c3hi);
                ffma2(A[2][1], vb.x, c2lo); ffma2(A[2][1], vb.y, c2hi);
                ffma2(A[3][1], vb.x, c3lo); ffma2(A[3][1], vb.y, c3hi);
                if (i < 7) { c2 = n2; c3 = n3; }
            }
            float S[4][2];
#pragma unroll
            for (int g4 = 0; g4 < 4; g4++)
#pragma unroll
                for (int s = 0; s < 2; s++) {
                    const float2 f = unpackf2(A[g4][s]);
                    float v = f.x + f.y;
                    v += __shfl_xor_sync(0xffffffffu, v, 1);
                    v += __shfl_xor_sync(0xffffffffu, v, 2);
                    S[g4][s] = v;
                }
            if (t >= 1 && k1 < 2) {
                const int s = k1;
                const float gi = S[0][s] + bi;
                const float gf = S[1][s] + bf_;
                const float gg = S[2][s] + bg;
                const float go = S[3][s] + bo;
                c_st = fsig(gf) * c_st + fsig(gi) * ftanh(gg);
                h_last = fsig(go) * ftanh(c_st);
                ubuf[nb_][s][1][l1] = h_last;
            }
        }
        __syncthreads();
    }

    // FC + sigmoid on h2[T-1]
    if (!isL0 && k1 < 2) red[k1][l1] = h_last * w_fc[l1];
    __syncthreads();
    if (tid < 64) {
        const int s_ = tid >> 5, ln = tid & 31;
        float p = red[s_][ln] + red[s_][ln + 32];
#pragma unroll
        for (int o = 16; o > 0; o >>= 1)
            p += __shfl_down_sync(0xffffffffu, p, o);
        if (ln == 0) out[b0 + s_] = fsig(p + b_fc[0]);
    }
}

extern "C" void kernel_launch(void* const* d_in, const int* in_sizes, int n_in,
                              void* d_out, int out_size) {
    const float* x       = (const float*)d_in[0];
    const float* w_ih_l0 = (const float*)d_in[1];
    const float* w_hh_l0 = (const float*)d_in[2];
    const float* b_ih_l0 = (const float*)d_in[3];
    const float* b_hh_l0 = (const float*)d_in[4];
    const float* w_ih_l1 = (const float*)d_in[5];
    const float* w_hh_l1 = (const float*)d_in[6];
    const float* b_ih_l1 = (const float*)d_in[7];
    const float* b_hh_l1 = (const float*)d_in[8];
    const float* w_fc    = (const float*)d_in[9];
    const float* b_fc    = (const float*)d_in[10];
    float* out = (float*)d_out;

    float* gx0;
    cudaGetSymbolAddress((void**)&gx0, g_gx0);

    gate_gemm<ND0><<<NM / 64, 256>>>(x, w_ih_l0, b_ih_l0, b_hh_l0, gx0);
    pack_w1<<<1, 256>>>(w_ih_l1, w_hh_l1);
    lstm_fused<<<NB / 2, 512>>>(gx0, w_hh_l0, w_ih_l1, w_hh_l1,
                                b_ih_l1, b_hh_l1, w_fc, b_fc, out);
}

// round 8
// speedup vs baseline: 1.3853x; 1.3853x over previous
#include <cuda_runtime.h>

#define NB 256
#define NT 1024
#define ND0 32
#define NH 64
#define NM (NB * NT)

__device__ float g_gx0[(size_t)NM * 256];   // L0 gate pre-activations [tok][gate]

using ull = unsigned long long;

__device__ __forceinline__ void ffma2(ull& d, ull a, ull b) {
    asm("fma.rn.f32x2 %0, %1, %2, %0;" : "+l"(d) : "l"(a), "l"(b));
}
__device__ __forceinline__ ull packf2(float x, float y) {
    ull r; asm("mov.b64 %0, {%1, %2};" : "=l"(r) : "f"(x), "f"(y)); return r;
}
__device__ __forceinline__ float2 unpackf2(ull v) {
    float2 f; asm("mov.b64 {%0, %1}, %2;" : "=f"(f.x), "=f"(f.y) : "l"(v)); return f;
}
__device__ __forceinline__ float ftanh(float x) {
    float y; asm("tanh.approx.f32 %0, %1;" : "=f"(y) : "f"(x)); return y;
}
__device__ __forceinline__ float fsig(float x) {
    return fmaf(0.5f, ftanh(0.5f * x), 0.5f);
}
__device__ __forceinline__ void cp_async16(void* s, const void* g) {
    unsigned sa = (unsigned)__cvta_generic_to_shared(s);
    asm volatile("cp.async.cg.shared.global [%0], [%1], 16;" :: "r"(sa), "l"(g));
}

// ===================== layer-0 gate GEMM, register-tiled =====================
// CTA: 64 tokens x 256 gates, K=32. Thread = 8 tokens x 8 gates (32 f32x2 accs).
// x staged PRE-DUPLICATED as f32x2 pairs; weights transposed to smem.
// Per k: 6 LDS.128 + 32 ffma2 (vs 16 LDS / 32 ffma2 before) -> FMA/issue bound.
__global__ __launch_bounds__(256) void gate_gemm32(
    const float* __restrict__ X,     // [M][32]
    const float* __restrict__ w_ih,  // [256][32]
    const float* __restrict__ b_ih,
    const float* __restrict__ b_hh,
    float* __restrict__ gx)          // [M][256]
{
    __shared__ __align__(16) ull   xdup[32][66];   // [k][tok] (x,x) pairs
    __shared__ __align__(16) float wT[32][264];    // [k][gate]

    const int tid = threadIdx.x;
    const size_t tok0 = (size_t)blockIdx.x * 64;

    // stage x (dup) : 512 float4 over 256 threads
#pragma unroll
    for (int j = 0; j < 2; j++) {
        const int idx4 = tid + j * 256;            // over [tok][8]
        const int tau = idx4 >> 3, kc = idx4 & 7;
        const float4 v = reinterpret_cast<const float4*>(X + (tok0 + tau) * 32)[kc];
        xdup[4 * kc + 0][tau] = packf2(v.x, v.x);
        xdup[4 * kc + 1][tau] = packf2(v.y, v.y);
        xdup[4 * kc + 2][tau] = packf2(v.z, v.z);
        xdup[4 * kc + 3][tau] = packf2(v.w, v.w);
    }
    // stage weights transposed: thread g scatters its row
    {
        const float4* wr = reinterpret_cast<const float4*>(w_ih + tid * 32);
#pragma unroll
        for (int c = 0; c < 8; c++) {
            const float4 v = wr[c];
            wT[4 * c + 0][tid] = v.x;
            wT[4 * c + 1][tid] = v.y;
            wT[4 * c + 2][tid] = v.z;
            wT[4 * c + 3][tid] = v.w;
        }
    }

    const int tokg = tid & 7;        // token group
    const int gg   = tid >> 3;       // gate group
    const int t0 = tokg * 8, g0 = gg * 8;

    ull acc[8][4];
#pragma unroll
    for (int p = 0; p < 4; p++) {
        const ull bp = packf2(b_ih[g0 + 2 * p]     + b_hh[g0 + 2 * p],
                              b_ih[g0 + 2 * p + 1] + b_hh[g0 + 2 * p + 1]);
#pragma unroll
        for (int tk = 0; tk < 8; tk++) acc[tk][p] = bp;
    }

    __syncthreads();

#pragma unroll 4
    for (int k = 0; k < 32; k++) {
        const ulonglong2 wa = *reinterpret_cast<const ulonglong2*>(&wT[k][g0]);
        const ulonglong2 wb = *reinterpret_cast<const ulonglong2*>(&wT[k][g0 + 4]);
        const ull w01[4] = {wa.x, wa.y, wb.x, wb.y};
        const ulonglong2* xr = reinterpret_cast<const ulonglong2*>(&xdup[k][t0]);
#pragma unroll
        for (int h = 0; h < 4; h++) {
            const ulonglong2 xv = xr[h];
#pragma unroll
            for (int p = 0; p < 4; p++) {
                ffma2(acc[2 * h][p],     xv.x, w01[p]);
                ffma2(acc[2 * h + 1][p], xv.y, w01[p]);
            }
        }
    }

#pragma unroll
    for (int tk = 0; tk < 8; tk++) {
        ulonglong2* dst =
            reinterpret_cast<ulonglong2*>(gx + (tok0 + t0 + tk) * 256 + g0);
        dst[0] = make_ulonglong2(acc[tk][0], acc[tk][1]);
        dst[1] = make_ulonglong2(acc[tk][2], acc[tk][3]);
    }
}

// ===================== fused L0 + L1 recurrence (R6 known-good) ==========
__global__ __launch_bounds__(384) void lstm_fused(
    const float* __restrict__ gx0,    // [B][T][256] (with L0 biases)
    const float* __restrict__ w_hh0,  // [256][64]
    const float* __restrict__ w_ih1,  // [256][64]
    const float* __restrict__ w_hh1,  // [256][64]
    const float* __restrict__ b_ih1,  // [256]
    const float* __restrict__ b_hh1,  // [256]
    const float* __restrict__ w_fc,   // [64]
    const float* __restrict__ b_fc,   // [1]
    float* __restrict__ out)          // [B]
{
    constexpr int PF  = 7;
    constexpr int SL  = 36;
    constexpr int USZ = 4 * SL;

    __shared__ __align__(16) float ubuf[2][2][USZ];
    __shared__ __align__(16) float gxs[8][2][256];
    __shared__ float red[2][NH];

    const int tid  = threadIdx.x;
    const int b0   = blockIdx.x * 2;
    const bool isL0 = (tid < 128);

    for (int i = tid; i < 2 * 2 * USZ; i += 384)
        (&ubuf[0][0][0])[i] = 0.0f;

    const int l0 = tid >> 1, h0 = tid & 1;
    const int rt = tid - 128;
    const int k1 = rt & 3, l1 = rt >> 2;

    ull w[4][16];
    float bi = 0.f, bf_ = 0.f, bg = 0.f, bo = 0.f;
    if (isL0) {
#pragma unroll
        for (int g4 = 0; g4 < 4; g4++) {
            const int row = 64 * g4 + l0;
#pragma unroll
            for (int i = 0; i < 16; i++) {
                const int k = 32 * h0 + 2 * i;
                w[g4][i] = packf2(w_hh0[row * NH + k], w_hh0[row * NH + k + 1]);
            }
        }
    } else {
#pragma unroll
        for (int g4 = 0; g4 < 4; g4++) {
            const int row = 64 * g4 + l1;
#pragma unroll
            for (int i = 0; i < 16; i++) {
                const int kk = 32 * k1 + 2 * i;
                const float a = (kk < 64) ? w_ih1[row * 64 + kk]
                                          : w_hh1[row * 64 + kk - 64];
                const float b = (kk < 64) ? w_ih1[row * 64 + kk + 1]
                                          : w_hh1[row * 64 + kk - 63];
                w[g4][i] = packf2(a, b);
            }
        }
        bi  = b_ih1[l1]       + b_hh1[l1];
        bf_ = b_ih1[64 + l1]  + b_hh1[64 + l1];
        bg  = b_ih1[128 + l1] + b_hh1[128 + l1];
        bo  = b_ih1[192 + l1] + b_hh1[192 + l1];
    }

    const int ls = tid >> 6, li = tid & 63;
    const float* gsrc = gx0 + ((size_t)(b0 + ls) * NT) * 256 + li * 4;
    if (isL0) {
#pragma unroll
        for (int p = 0; p < PF; p++) {
            cp_async16(&gxs[p][ls][li * 4], gsrc + (size_t)p * 256);
            asm volatile("cp.async.commit_group;");
        }
        asm volatile("cp.async.wait_group %0;" :: "n"(PF - 1));
    }
    __syncthreads();

    float c0 = 0.f, c1 = 0.f;
    float c_s = 0.f, h_last = 0.f;

#pragma unroll 1
    for (int t = 0; t <= NT; t++) {
        const int cb = t & 1, nb_ = (t + 1) & 1;

        if (isL0) {
            const ulonglong2* u0 = reinterpret_cast<const ulonglong2*>(&ubuf[cb][0][h0 * SL]);
            const ulonglong2* u1 = reinterpret_cast<const ulonglong2*>(&ubuf[cb][1][h0 * SL]);
            ull A[4][2];
#pragma unroll
            for (int g4 = 0; g4 < 4; g4++) { A[g4][0] = 0; A[g4][1] = 0; }
#pragma unroll
            for (int i = 0; i < 8; i++) {
                const ulonglong2 va = u0[i];
                const ulonglong2 vb = u1[i];
#pragma unroll
                for (int g4 = 0; g4 < 4; g4++) {
                    ffma2(A[g4][0], va.x, w[g4][2 * i]);
                    ffma2(A[g4][0], va.y, w[g4][2 * i + 1]);
                    ffma2(A[g4][1], vb.x, w[g4][2 * i]);
                    ffma2(A[g4][1], vb.y, w[g4][2 * i + 1]);
                }
            }
            float S[4][2];
#pragma unroll
            for (int g4 = 0; g4 < 4; g4++)
#pragma unroll
                for (int s = 0; s < 2; s++) {
                    const float2 f = unpackf2(A[g4][s]);
                    float v = f.x + f.y;
                    v += __shfl_xor_sync(0xffffffffu, v, 1);
                    S[g4][s] = v;
                }
            if (h0 == 0 && t < NT) {
                const float* gb0 = &gxs[t & 7][0][0];
                const float* gb1 = &gxs[t & 7][1][0];
                {
                    const float gi = S[0][0] + gb0[l0];
                    const float gf = S[1][0] + gb0[64 + l0];
                    const float gg = S[2][0] + gb0[128 + l0];
                    const float go = S[3][0] + gb0[192 + l0];
                    c0 = fsig(gf) * c0 + fsig(gi) * ftanh(gg);
                    ubuf[nb_][0][(l0 >> 5) * SL + (l0 & 31)] = fsig(go) * ftanh(c0);
                }
                {
                    const float gi = S[0][1] + gb1[l0];
                    const float gf = S[1][1] + gb1[64 + l0];
                    const float gg = S[2][1] + gb1[128 + l0];
                    const float go = S[3][1] + gb1[192 + l0];
                    c1 = fsig(gf) * c1 + fsig(gi) * ftanh(gg);
                    ubuf[nb_][1][(l0 >> 5) * SL + (l0 & 31)] = fsig(go) * ftanh(c1);
                }
            }
            if (t + PF < NT)
                cp_async16(&gxs[(t + PF) & 7][ls][li * 4], gsrc + (size_t)(t + PF) * 256);
            asm volatile("cp.async.commit_group;");
            asm volatile("cp.async.wait_group %0;" :: "n"(PF - 1));
        } else {
            const ulonglong2* uA = reinterpret_cast<const ulonglong2*>(&ubuf[cb][0][k1 * SL]);
            const ulonglong2* uB = reinterpret_cast<const ulonglong2*>(&ubuf[cb][1][k1 * SL]);
            ull A[4][2];
#pragma unroll
            for (int g4 = 0; g4 < 4; g4++) { A[g4][0] = 0; A[g4][1] = 0; }
#pragma unroll
            for (int i = 0; i < 8; i++) {
                const ulonglong2 va = uA[i];
                const ulonglong2 vb = uB[i];
#pragma unroll
                for (int g4 = 0; g4 < 4; g4++) {
                    ffma2(A[g4][0], va.x, w[g4][2 * i]);
                    ffma2(A[g4][0], va.y, w[g4][2 * i + 1]);
                    ffma2(A[g4][1], vb.x, w[g4][2 * i]);
                    ffma2(A[g4][1], vb.y, w[g4][2 * i + 1]);
                }
            }
            float S[4][2];
#pragma unroll
            for (int g4 = 0; g4 < 4; g4++)
#pragma unroll
                for (int s = 0; s < 2; s++) {
                    const float2 f = unpackf2(A[g4][s]);
                    float v = f.x + f.y;
                    v += __shfl_xor_sync(0xffffffffu, v, 1);
                    v += __shfl_xor_sync(0xffffffffu, v, 2);
                    S[g4][s] = v;
                }
            if (t >= 1 && k1 < 2) {
                const int sel = k1;
                const float gi = S[0][sel] + bi;
                const float gf = S[1][sel] + bf_;
                const float gg = S[2][sel] + bg;
                const float go = S[3][sel] + bo;
                c_s = fsig(gf) * c_s + fsig(gi) * ftanh(gg);
                h_last = fsig(go) * ftanh(c_s);
                ubuf[nb_][sel][(2 + (l1 >> 5)) * SL + (l1 & 31)] = h_last;
            }
        }
        __syncthreads();
    }

    if (!isL0 && k1 < 2) red[k1][l1] = h_last * w_fc[l1];
    __syncthreads();
    if (tid < 64) {
        const int s_ = tid >> 5, ln = tid & 31;
        float p = red[s_][ln] + red[s_][ln + 32];
#pragma unroll
        for (int o = 16; o > 0; o >>= 1)
            p += __shfl_down_sync(0xffffffffu, p, o);
        if (ln == 0) out[b0 + s_] = fsig(p + b_fc[0]);
    }
}

extern "C" void kernel_launch(void* const* d_in, const int* in_sizes, int n_in,
                              void* d_out, int out_size) {
    const float* x       = (const float*)d_in[0];
    const float* w_ih_l0 = (const float*)d_in[1];
    const float* w_hh_l0 = (const float*)d_in[2];
    const float* b_ih_l0 = (const float*)d_in[3];
    const float* b_hh_l0 = (const float*)d_in[4];
    const float* w_ih_l1 = (const float*)d_in[5];
    const float* w_hh_l1 = (const float*)d_in[6];
    const float* b_ih_l1 = (const float*)d_in[7];
    const float* b_hh_l1 = (const float*)d_in[8];
    const float* w_fc    = (const float*)d_in[9];
    const float* b_fc    = (const float*)d_in[10];
    float* out = (float*)d_out;

    float* gx0;
    cudaGetSymbolAddress((void**)&gx0, g_gx0);

    gate_gemm32<<<NM / 64, 256>>>(x, w_ih_l0, b_ih_l0, b_hh_l0, gx0);
    lstm_fused<<<NB / 2, 384>>>(gx0, w_hh_l0, w_ih_l1, w_hh_l1,
                                b_ih_l1, b_hh_l1, w_fc, b_fc, out);
}

// round 11
// speedup vs baseline: 1.5301x; 1.1045x over previous
#include <cuda_runtime.h>

#define NB 256
#define NT 1024
#define ND0 32
#define NH 64
#define NM (NB * NT)

__device__ float g_gx0[(size_t)NM * 256];   // L0 gate pre-activations [tok][gate]

using ull = unsigned long long;

__device__ __forceinline__ void ffma2(ull& d, ull a, ull b) {
    asm("fma.rn.f32x2 %0, %1, %2, %0;" : "+l"(d) : "l"(a), "l"(b));
}
__device__ __forceinline__ ull packf2(float x, float y) {
    ull r; asm("mov.b64 %0, {%1, %2};" : "=l"(r) : "f"(x), "f"(y)); return r;
}
__device__ __forceinline__ float2 unpackf2(ull v) {
    float2 f; asm("mov.b64 {%0, %1}, %2;" : "=f"(f.x), "=f"(f.y) : "l"(v)); return f;
}
__device__ __forceinline__ float ftanh(float x) {
    float y; asm("tanh.approx.f32 %0, %1;" : "=f"(y) : "f"(x)); return y;
}
__device__ __forceinline__ float fsig(float x) {
    return fmaf(0.5f, ftanh(0.5f * x), 0.5f);
}
__device__ __forceinline__ void cp_async16(void* s, const void* g) {
    unsigned sa = (unsigned)__cvta_generic_to_shared(s);
    asm volatile("cp.async.cg.shared.global [%0], [%1], 16;" :: "r"(sa), "l"(g));
}

// ===================== layer-0 gate GEMM, register-tiled, bank-fixed =====================
__global__ __launch_bounds__(256) void gate_gemm32(
    const float* __restrict__ X,     // [M][32]
    const float* __restrict__ w_ih,  // [256][32]
    const float* __restrict__ b_ih,
    const float* __restrict__ b_hh,
    float* __restrict__ gx)          // [M][256]
{
    __shared__ __align__(16) ull   xdup[32][80];   // [k][skewed tok]
    __shared__ __align__(16) float wT[32][264];    // [k][gate]

    const int tid = threadIdx.x;
    const size_t tok0 = (size_t)blockIdx.x * 64;

#pragma unroll
    for (int j = 0; j < 2; j++) {
        const int idx4 = tid + j * 256;
        const int tau = idx4 >> 3, kc = idx4 & 7;
        const int ts = tau + 2 * (tau >> 3);       // skewed slot
        const float4 v = reinterpret_cast<const float4*>(X + (tok0 + tau) * 32)[kc];
        xdup[4 * kc + 0][ts] = packf2(v.x, v.x);
        xdup[4 * kc + 1][ts] = packf2(v.y, v.y);
        xdup[4 * kc + 2][ts] = packf2(v.z, v.z);
        xdup[4 * kc + 3][ts] = packf2(v.w, v.w);
    }
    {
        const float4* wr = reinterpret_cast<const float4*>(w_ih + tid * 32);
#pragma unroll
        for (int c = 0; c < 8; c++) {
            const float4 v = wr[c];
            wT[4 * c + 0][tid] = v.x;
            wT[4 * c + 1][tid] = v.y;
            wT[4 * c + 2][tid] = v.z;
            wT[4 * c + 3][tid] = v.w;
        }
    }

    const int tokg = tid & 7;
    const int gg   = tid >> 3;
    const int t0s = tokg * 10;        // skewed group base
    const int t0  = tokg * 8;
    const int g0  = gg * 8;

    ull acc[8][4];
#pragma unroll
    for (int p = 0; p < 4; p++) {
        const ull bp = packf2(b_ih[g0 + 2 * p]     + b_hh[g0 + 2 * p],
                              b_ih[g0 + 2 * p + 1] + b_hh[g0 + 2 * p + 1]);
#pragma unroll
        for (int tk = 0; tk < 8; tk++) acc[tk][p] = bp;
    }

    __syncthreads();

#pragma unroll 4
    for (int k = 0; k < 32; k++) {
        const ulonglong2 wa = *reinterpret_cast<const ulonglong2*>(&wT[k][g0]);
        const ulonglong2 wb = *reinterpret_cast<const ulonglong2*>(&wT[k][g0 + 4]);
        const ull w01[4] = {wa.x, wa.y, wb.x, wb.y};
        const ulonglong2* xr = reinterpret_cast<const ulonglong2*>(&xdup[k][t0s]);
#pragma unroll
        for (int h = 0; h < 4; h++) {
            const ulonglong2 xv = xr[h];
#pragma unroll
            for (int p = 0; p < 4; p++) {
                ffma2(acc[2 * h][p],     xv.x, w01[p]);
                ffma2(acc[2 * h + 1][p], xv.y, w01[p]);
            }
        }
    }

#pragma unroll
    for (int tk = 0; tk < 8; tk++) {
        ulonglong2* dst =
            reinterpret_cast<ulonglong2*>(gx + (tok0 + t0 + tk) * 256 + g0);
        dst[0] = make_ulonglong2(acc[tk][0], acc[tk][1]);
        dst[1] = make_ulonglong2(acc[tk][2], acc[tk][3]);
    }
}

// ===================== fused L0 + L1 recurrence, named-barrier pipelined ==========
// Liveness-fixed: ONE bar2 prologue arrive (256 < 384 cannot eager-release).
// Steady state (simulated): L0 p: [dot p | cell p] -> sync2 (needs L1 arrive p)
//   -> write slot p&3 -> arrive1 -> bar3(L0).
// L1 p: sync1 (needs L0 arrive p-1) -> read slots -> arrive2 -> reduce/cell
//   -> bar4(L1).
// bar1 never holds >1 pending arrive; bar2 capped at 384; no eager release.
__global__ __launch_bounds__(384) void lstm_fused(
    const float* __restrict__ gx0,    // [B][T][256] (with L0 biases)
    const float* __restrict__ w_hh0,  // [256][64]
    const float* __restrict__ w_ih1,  // [256][64]
    const float* __restrict__ w_hh1,  // [256][64]
    const float* __restrict__ b_ih1,  // [256]
    const float* __restrict__ b_hh1,  // [256]
    const float* __restrict__ w_fc,   // [64]
    const float* __restrict__ b_fc,   // [1]
    float* __restrict__ out)          // [B]
{
    constexpr int PF = 7;

    __shared__ __align__(16) float h1r[4][2][72];   // h1 ring [slot][sample][64+pad]
    __shared__ __align__(16) float h2p[2][2][72];   // h2 ping-pong
    __shared__ __align__(16) float gxs[8][2][256];
    __shared__ float red[2][NH];

    const int tid  = threadIdx.x;
    const int b0   = blockIdx.x * 2;
    const bool isL0 = (tid < 128);

    for (int i = tid; i < 4 * 2 * 72; i += 384) (&h1r[0][0][0])[i] = 0.0f;
    for (int i = tid; i < 2 * 2 * 72; i += 384) (&h2p[0][0][0])[i] = 0.0f;

    const int l0 = tid >> 1, h0 = tid & 1;
    const int rt = tid - 128;
    const int k1 = rt & 3, l1 = rt >> 2;

    ull w[4][16];
    float bi = 0.f, bf_ = 0.f, bg = 0.f, bo = 0.f;
    if (isL0) {
#pragma unroll
        for (int g4 = 0; g4 < 4; g4++) {
            const int row = 64 * g4 + l0;
#pragma unroll
            for (int i = 0; i < 16; i++) {
                const int k = 32 * h0 + 2 * i;
                w[g4][i] = packf2(w_hh0[row * NH + k], w_hh0[row * NH + k + 1]);
            }
        }
    } else {
#pragma unroll
        for (int g4 = 0; g4 < 4; g4++) {
            const int row = 64 * g4 + l1;
#pragma unroll
            for (int i = 0; i < 16; i++) {
                const int kk = 32 * k1 + 2 * i;
                const float a = (kk < 64) ? w_ih1[row * 64 + kk]
                                          : w_hh1[row * 64 + kk - 64];
                const float b = (kk < 64) ? w_ih1[row * 64 + kk + 1]
                                          : w_hh1[row * 64 + kk - 63];
                w[g4][i] = packf2(a, b);
            }
        }
        bi  = b_ih1[l1]       + b_hh1[l1];
        bf_ = b_ih1[64 + l1]  + b_hh1[64 + l1];
        bg  = b_ih1[128 + l1] + b_hh1[128 + l1];
        bo  = b_ih1[192 + l1] + b_hh1[192 + l1];
    }

    const int ls = tid >> 6, li = tid & 63;
    const float* gsrc = gx0 + ((size_t)(b0 + ls) * NT) * 256 + li * 4;
    if (isL0) {
#pragma unroll
        for (int p = 0; p < PF; p++) {
            cp_async16(&gxs[p][ls][li * 4], gsrc + (size_t)p * 256);
            asm volatile("cp.async.commit_group;");
        }
        asm volatile("cp.async.wait_group %0;" :: "n"(PF - 1));
    }
    __syncthreads();

    // prologue: EXACTLY ONE bar2 arrive round (the only safe slack amount)
    if (!isL0)
        asm volatile("bar.arrive 2, 384;" ::: "memory");

    float c0 = 0.f, c1 = 0.f;          // L0 cell states
    float c_s = 0.f, h_last = 0.f;     // L1 cell state

#pragma unroll 1
    for (int p = 0; p <= NT; p++) {
        if (isL0) {
            if (p < NT) {
                const int rs = (p + 3) & 3;      // (p-1)&3 : h1(p-1); zeros at p=0
                const ulonglong2* u0 =
                    reinterpret_cast<const ulonglong2*>(&h1r[rs][0][h0 * 36]);
                const ulonglong2* u1 =
                    reinterpret_cast<const ulonglong2*>(&h1r[rs][1][h0 * 36]);
                ull A[4][2];
#pragma unroll
                for (int g4 = 0; g4 < 4; g4++) { A[g4][0] = 0; A[g4][1] = 0; }
#pragma unroll
                for (int i = 0; i < 8; i++) {
                    const ulonglong2 va = u0[i];
                    const ulonglong2 vb = u1[i];
#pragma unroll
                    for (int g4 = 0; g4 < 4; g4++) {
                        ffma2(A[g4][0], va.x, w[g4][2 * i]);
                        ffma2(A[g4][0], va.y, w[g4][2 * i + 1]);
                        ffma2(A[g4][1], vb.x, w[g4][2 * i]);
                        ffma2(A[g4][1], vb.y, w[g4][2 * i + 1]);
                    }
                }
                float S[4][2];
#pragma unroll
                for (int g4 = 0; g4 < 4; g4++)
#pragma unroll
                    for (int s = 0; s < 2; s++) {
                        const float2 f = unpackf2(A[g4][s]);
                        float v = f.x + f.y;
                        v += __shfl_xor_sync(0xffffffffu, v, 1);
                        S[g4][s] = v;
                    }
                float hv0 = 0.f, hv1 = 0.f;
                if (h0 == 0) {
                    const float* gb0 = &gxs[p & 7][0][0];
                    const float* gb1 = &gxs[p & 7][1][0];
                    {
                        const float gi = S[0][0] + gb0[l0];
                        const float gf = S[1][0] + gb0[64 + l0];
                        const float gg = S[2][0] + gb0[128 + l0];
                        const float go = S[3][0] + gb0[192 + l0];
                        c0 = fsig(gf) * c0 + fsig(gi) * ftanh(gg);
                        hv0 = fsig(go) * ftanh(c0);
                    }
                    {
                        const float gi = S[0][1] + gb1[l0];
                        const float gf = S[1][1] + gb1[64 + l0];
                        const float gg = S[2][1] + gb1[128 + l0];
                        const float go = S[3][1] + gb1[192 + l0];
                        c1 = fsig(gf) * c1 + fsig(gi) * ftanh(gg);
                        hv1 = fsig(go) * ftanh(c1);
                    }
                }
                asm volatile("bar.sync 2, 384;" ::: "memory");   // slot p&3 free
                if (h0 == 0) {
                    const int off = (l0 >> 5) * 36 + (l0 & 31);
                    h1r[p & 3][0][off] = hv0;
                    h1r[p & 3][1][off] = hv1;
                }
                asm volatile("bar.arrive 1, 384;" ::: "memory"); // h1(p) ready
                asm volatile("bar.sync 3, 128;" ::: "memory");   // L0 visibility
                if (p + PF < NT)
                    cp_async16(&gxs[(p + PF) & 7][ls][li * 4],
                               gsrc + (size_t)(p + PF) * 256);
                asm volatile("cp.async.commit_group;");
                asm volatile("cp.async.wait_group %0;" :: "n"(PF - 1));
            }
        } else {
            if (p >= 1) {
                asm volatile("bar.sync 1, 384;" ::: "memory");   // h1(p-1) ready
                const int rs = (p + 3) & 3;                      // h1 slot (p-1)&3
                const float* baseA = (k1 < 2)
                    ? &h1r[rs][0][(k1 & 1) * 36]
                    : &h2p[p & 1][0][(k1 & 1) * 36];             // h2(p-2)
                const ulonglong2* uA = reinterpret_cast<const ulonglong2*>(baseA);
                const ulonglong2* uB = reinterpret_cast<const ulonglong2*>(baseA + 72);
                ull A[4][2];
#pragma unroll
                for (int g4 = 0; g4 < 4; g4++) { A[g4][0] = 0; A[g4][1] = 0; }
#pragma unroll
                for (int i = 0; i < 8; i++) {
                    const ulonglong2 va = uA[i];
                    const ulonglong2 vb = uB[i];
#pragma unroll
                    for (int g4 = 0; g4 < 4; g4++) {
                        ffma2(A[g4][0], va.x, w[g4][2 * i]);
                        ffma2(A[g4][0], va.y, w[g4][2 * i + 1]);
                        ffma2(A[g4][1], vb.x, w[g4][2 * i]);
                        ffma2(A[g4][1], vb.y, w[g4][2 * i + 1]);
                    }
                }
                asm volatile("bar.arrive 2, 384;" ::: "memory"); // reads done
                float S[4][2];
#pragma unroll
                for (int g4 = 0; g4 < 4; g4++)
#pragma unroll
                    for (int s = 0; s < 2; s++) {
                        const float2 f = unpackf2(A[g4][s]);
                        float v = f.x + f.y;
                        v += __shfl_xor_sync(0xffffffffu, v, 1);
                        v += __shfl_xor_sync(0xffffffffu, v, 2);
                        S[g4][s] = v;
                    }
                if (k1 < 2) {
                    const int sel = k1;
                    const float gi = S[0][sel] + bi;
                    const float gf = S[1][sel] + bf_;
                    const float gg = S[2][sel] + bg;
                    const float go = S[3][sel] + bo;
                    c_s = fsig(gf) * c_s + fsig(gi) * ftanh(gg);
                    h_last = fsig(go) * ftanh(c_s);
                    h2p[(p + 1) & 1][sel][(l1 >> 5) * 36 + (l1 & 31)] = h_last;
                }
                asm volatile("bar.sync 4, 256;" ::: "memory");   // L1 visibility
            }
        }
    }
    __syncthreads();

    if (!isL0 && k1 < 2) red[k1][l1] = h_last * w_fc[l1];
    __syncthreads();
    if (tid < 64) {
        const int s_ = tid >> 5, ln = tid & 31;
        float p = red[s_][ln] + red[s_][ln + 32];
#pragma unroll
        for (int o = 16; o > 0; o >>= 1)
            p += __shfl_down_sync(0xffffffffu, p, o);
        if (ln == 0) out[b0 + s_] = fsig(p + b_fc[0]);
    }
}

extern "C" void kernel_launch(void* const* d_in, const int* in_sizes, int n_in,
                              void* d_out, int out_size) {
    const float* x       = (const float*)d_in[0];
    const float* w_ih_l0 = (const float*)d_in[1];
    const float* w_hh_l0 = (const float*)d_in[2];
    const float* b_ih_l0 = (const float*)d_in[3];
    const float* b_hh_l0 = (const float*)d_in[4];
    const float* w_ih_l1 = (const float*)d_in[5];
    const float* w_hh_l1 = (const float*)d_in[6];
    const float* b_ih_l1 = (const float*)d_in[7];
    const float* b_hh_l1 = (const float*)d_in[8];
    const float* w_fc    = (const float*)d_in[9];
    const float* b_fc    = (const float*)d_in[10];
    float* out = (float*)d_out;

    float* gx0;
    cudaGetSymbolAddress((void**)&gx0, g_gx0);

    gate_gemm32<<<NM / 64, 256>>>(x, w_ih_l0, b_ih_l0, b_hh_l0, gx0);
    lstm_fused<<<NB / 2, 384>>>(gx0, w_hh_l0, w_ih_l1, w_hh_l1,
                                b_ih_l1, b_hh_l1, w_fc, b_fc, out);
}

// round 12
// speedup vs baseline: 1.6360x; 1.0692x over previous
#include <cuda_runtime.h>

#define NB 256
#define NT 1024
#define ND0 32
#define NH 64
#define NM (NB * NT)

__device__ float g_gx0[(size_t)NM * 256];   // L0 gate pre-activations [tok][gate]

using ull = unsigned long long;

__device__ __forceinline__ void ffma2(ull& d, ull a, ull b) {
    asm("fma.rn.f32x2 %0, %1, %2, %0;" : "+l"(d) : "l"(a), "l"(b));
}
__device__ __forceinline__ ull packf2(float x, float y) {
    ull r; asm("mov.b64 %0, {%1, %2};" : "=l"(r) : "f"(x), "f"(y)); return r;
}
__device__ __forceinline__ float2 unpackf2(ull v) {
    float2 f; asm("mov.b64 {%0, %1}, %2;" : "=f"(f.x), "=f"(f.y) : "l"(v)); return f;
}
__device__ __forceinline__ float ftanh(float x) {
    float y; asm("tanh.approx.f32 %0, %1;" : "=f"(y) : "f"(x)); return y;
}
__device__ __forceinline__ float fsig(float x) {
    return fmaf(0.5f, ftanh(0.5f * x), 0.5f);
}
__device__ __forceinline__ void cp_async16(void* s, const void* g) {
    unsigned sa = (unsigned)__cvta_generic_to_shared(s);
    asm volatile("cp.async.cg.shared.global [%0], [%1], 16;" :: "r"(sa), "l"(g));
}

// ===================== layer-0 gate GEMM (R11 proven, unchanged) =====================
__global__ __launch_bounds__(256) void gate_gemm32(
    const float* __restrict__ X,     // [M][32]
    const float* __restrict__ w_ih,  // [256][32]
    const float* __restrict__ b_ih,
    const float* __restrict__ b_hh,
    float* __restrict__ gx)          // [M][256]
{
    __shared__ __align__(16) ull   xdup[32][80];
    __shared__ __align__(16) float wT[32][264];

    const int tid = threadIdx.x;
    const size_t tok0 = (size_t)blockIdx.x * 64;

#pragma unroll
    for (int j = 0; j < 2; j++) {
        const int idx4 = tid + j * 256;
        const int tau = idx4 >> 3, kc = idx4 & 7;
        const int ts = tau + 2 * (tau >> 3);
        const float4 v = reinterpret_cast<const float4*>(X + (tok0 + tau) * 32)[kc];
        xdup[4 * kc + 0][ts] = packf2(v.x, v.x);
        xdup[4 * kc + 1][ts] = packf2(v.y, v.y);
        xdup[4 * kc + 2][ts] = packf2(v.z, v.z);
        xdup[4 * kc + 3][ts] = packf2(v.w, v.w);
    }
    {
        const float4* wr = reinterpret_cast<const float4*>(w_ih + tid * 32);
#pragma unroll
        for (int c = 0; c < 8; c++) {
            const float4 v = wr[c];
            wT[4 * c + 0][tid] = v.x;
            wT[4 * c + 1][tid] = v.y;
            wT[4 * c + 2][tid] = v.z;
            wT[4 * c + 3][tid] = v.w;
        }
    }

    const int tokg = tid & 7;
    const int gg   = tid >> 3;
    const int t0s = tokg * 10;
    const int t0  = tokg * 8;
    const int g0  = gg * 8;

    ull acc[8][4];
#pragma unroll
    for (int p = 0; p < 4; p++) {
        const ull bp = packf2(b_ih[g0 + 2 * p]     + b_hh[g0 + 2 * p],
                              b_ih[g0 + 2 * p + 1] + b_hh[g0 + 2 * p + 1]);
#pragma unroll
        for (int tk = 0; tk < 8; tk++) acc[tk][p] = bp;
    }

    __syncthreads();

#pragma unroll 4
    for (int k = 0; k < 32; k++) {
        const ulonglong2 wa = *reinterpret_cast<const ulonglong2*>(&wT[k][g0]);
        const ulonglong2 wb = *reinterpret_cast<const ulonglong2*>(&wT[k][g0 + 4]);
        const ull w01[4] = {wa.x, wa.y, wb.x, wb.y};
        const ulonglong2* xr = reinterpret_cast<const ulonglong2*>(&xdup[k][t0s]);
#pragma unroll
        for (int h = 0; h < 4; h++) {
            const ulonglong2 xv = xr[h];
#pragma unroll
            for (int p = 0; p < 4; p++) {
                ffma2(acc[2 * h][p],     xv.x, w01[p]);
                ffma2(acc[2 * h + 1][p], xv.y, w01[p]);
            }
        }
    }

#pragma unroll
    for (int tk = 0; tk < 8; tk++) {
        ulonglong2* dst =
            reinterpret_cast<ulonglong2*>(gx + (tok0 + t0 + tk) * 256 + g0);
        dst[0] = make_ulonglong2(acc[tk][0], acc[tk][1]);
        dst[1] = make_ulonglong2(acc[tk][2], acc[tk][3]);
    }
}

// ===================== fused L0 + L1, BROADCAST u-reads =====================
// 384 threads, 2 samples/CTA, lag-1 (L0 step t, L1 step t-1).
// Warp-constant k-slices: every u read is a warp-uniform LDS.128 broadcast
// (1 crossbar cyc vs 4). k-partials combine through tiny smem buffers.
//   L0: tid<128:  q = tid>>6 (k-half, warp-const), l = tid&63.
//       Thread: 4 gates of lane l, k in [32q,32q+32), both samples.
//       q==0 threads combine partials (+gx) and run the cell.
//   L1: rt=tid-128: kq = rt>>6 (k-quarter of K=128), l = rt&63.
//       kq==0 threads combine 3 partner partials (+bias) and run the cell.
// Two __syncthreads per step: A (partials visible), B (h visible).
__global__ __launch_bounds__(384) void lstm_fused(
    const float* __restrict__ gx0,    // [B][T][256] (with L0 biases)
    const float* __restrict__ w_hh0,  // [256][64]
    const float* __restrict__ w_ih1,  // [256][64]
    const float* __restrict__ w_hh1,  // [256][64]
    const float* __restrict__ b_ih1,  // [256]
    const float* __restrict__ b_hh1,  // [256]
    const float* __restrict__ w_fc,   // [64]
    const float* __restrict__ b_fc,   // [1]
    float* __restrict__ out)          // [B]
{
    constexpr int PF = 7;

    __shared__ __align__(16) float ubuf[2][2][128];     // [buf][sample][h1|h2]
    __shared__ __align__(16) float gxs[8][2][256];      // gx0 ring
    __shared__ __align__(16) float p0buf[2][64][4];     // L0 q=1 partials
    __shared__ __align__(16) float p1buf[3][2][64][4];  // L1 kq>=1 partials
    __shared__ float red[2][NH];

    const int tid  = threadIdx.x;
    const int b0   = blockIdx.x * 2;
    const bool isL0 = (tid < 128);

    for (int i = tid; i < 2 * 2 * 128; i += 384) (&ubuf[0][0][0])[i] = 0.0f;

    const int q  = (tid >> 6) & 1;     // L0 k-half   (warp-constant)
    const int rt = tid - 128;
    const int kq = rt >> 6;            // L1 k-quarter (warp-constant)
    const int l  = isL0 ? (tid & 63) : (rt & 63);

    // ---- weights: 4 gate rows x 32 floats (my k-slice) ----
    ull w[4][16];
    float bi = 0.f, bf_ = 0.f, bg = 0.f, bo = 0.f;
    if (isL0) {
#pragma unroll
        for (int g4 = 0; g4 < 4; g4++) {
            const int row = 64 * g4 + l;
#pragma unroll
            for (int i = 0; i < 16; i++) {
                const int k = 32 * q + 2 * i;
                w[g4][i] = packf2(w_hh0[row * NH + k], w_hh0[row * NH + k + 1]);
            }
        }
    } else {
#pragma unroll
        for (int g4 = 0; g4 < 4; g4++) {
            const int row = 64 * g4 + l;
#pragma unroll
            for (int i = 0; i < 16; i++) {
                const int kk = 32 * kq + 2 * i;
                const float a = (kk < 64) ? w_ih1[row * 64 + kk]
                                          : w_hh1[row * 64 + kk - 64];
                const float b = (kk < 64) ? w_ih1[row * 64 + kk + 1]
                                          : w_hh1[row * 64 + kk - 63];
                w[g4][i] = packf2(a, b);
            }
        }
        if (kq == 0) {
            bi  = b_ih1[l]       + b_hh1[l];
            bf_ = b_ih1[64 + l]  + b_hh1[64 + l];
            bg  = b_ih1[128 + l] + b_hh1[128 + l];
            bo  = b_ih1[192 + l] + b_hh1[192 + l];
        }
    }

    // gx ring loaders: L0 q==1 threads (tid 64..127), 2 chunks each
    const bool isload = isL0 && (q == 1);
    const float* gsrc0 = gx0 + ((size_t)(b0 + 0) * NT) * 256 + l * 4;
    const float* gsrc1 = gx0 + ((size_t)(b0 + 1) * NT) * 256 + l * 4;
    if (isload) {
#pragma unroll
        for (int p = 0; p < PF; p++) {
            cp_async16(&gxs[p][0][l * 4], gsrc0 + (size_t)p * 256);
            cp_async16(&gxs[p][1][l * 4], gsrc1 + (size_t)p * 256);
            asm volatile("cp.async.commit_group;");
        }
        asm volatile("cp.async.wait_group %0;" :: "n"(PF - 1));
    }
    __syncthreads();

    float c0 = 0.f, c1 = 0.f;          // L0 cell states   (q==0)
    float d0 = 0.f, d1 = 0.f;          // L1 cell states   (kq==0)
    float h_l0 = 0.f, h_l1 = 0.f;      // L1 last hidden

#pragma unroll 1
    for (int t = 0; t <= NT; t++) {
        const int cb = t & 1, nb_ = cb ^ 1;

        float P[4][2];
        const bool doL0 = isL0 && (t < NT);
        const bool doL1 = !isL0 && (t >= 1);

        if (doL0 || doL1) {
            const int base = isL0 ? 32 * q : 32 * kq;
            const ulonglong2* uA =
                reinterpret_cast<const ulonglong2*>(&ubuf[cb][0][base]);
            const ulonglong2* uB =
                reinterpret_cast<const ulonglong2*>(&ubuf[cb][1][base]);
            ull A[4][2];
#pragma unroll
            for (int g4 = 0; g4 < 4; g4++) { A[g4][0] = 0; A[g4][1] = 0; }
#pragma unroll
            for (int i = 0; i < 8; i++) {
                const ulonglong2 va = uA[i];   // warp-uniform broadcast
                const ulonglong2 vb = uB[i];
#pragma unroll
                for (int g4 = 0; g4 < 4; g4++) {
                    ffma2(A[g4][0], va.x, w[g4][2 * i]);
                    ffma2(A[g4][0], va.y, w[g4][2 * i + 1]);
                    ffma2(A[g4][1], vb.x, w[g4][2 * i]);
                    ffma2(A[g4][1], vb.y, w[g4][2 * i + 1]);
                }
            }
#pragma unroll
            for (int g4 = 0; g4 < 4; g4++)
#pragma unroll
                for (int s = 0; s < 2; s++) {
                    const float2 f = unpackf2(A[g4][s]);
                    P[g4][s] = f.x + f.y;
                }
            // export partials
            if (isL0) {
                if (q == 1) {
                    *reinterpret_cast<float4*>(&p0buf[0][l][0]) =
                        make_float4(P[0][0], P[1][0], P[2][0], P[3][0]);
                    *reinterpret_cast<float4*>(&p0buf[1][l][0]) =
                        make_float4(P[0][1], P[1][1], P[2][1], P[3][1]);
                }
            } else if (kq >= 1) {
                *reinterpret_cast<float4*>(&p1buf[kq - 1][0][l][0]) =
                    make_float4(P[0][0], P[1][0], P[2][0], P[3][0]);
                *reinterpret_cast<float4*>(&p1buf[kq - 1][1][l][0]) =
                    make_float4(P[0][1], P[1][1], P[2][1], P[3][1]);
            }
        }
        __syncthreads();   // A: partials visible

        if (doL0) {
            if (q == 0) {
                const float4 r0 = *reinterpret_cast<const float4*>(&p0buf[0][l][0]);
                const float4 r1 = *reinterpret_cast<const float4*>(&p0buf[1][l][0]);
                const float* gb0 = &gxs[t & 7][0][0];
                const float* gb1 = &gxs[t & 7][1][0];
                {
                    const float gi = P[0][0] + r0.x + gb0[l];
                    const float gf = P[1][0] + r0.y + gb0[64 + l];
                    const float gg = P[2][0] + r0.z + gb0[128 + l];
                    const float go = P[3][0] + r0.w + gb0[192 + l];
                    c0 = fsig(gf) * c0 + fsig(gi) * ftanh(gg);
                    ubuf[nb_][0][l] = fsig(go) * ftanh(c0);
                }
                {
                    const float gi = P[0][1] + r1.x + gb1[l];
                    const float gf = P[1][1] + r1.y + gb1[64 + l];
                    const float gg = P[2][1] + r1.z + gb1[128 + l];
                    const float go = P[3][1] + r1.w + gb1[192 + l];
                    c1 = fsig(gf) * c1 + fsig(gi) * ftanh(gg);
                    ubuf[nb_][1][l] = fsig(go) * ftanh(c1);
                }
            } else {
                if (t + PF < NT) {
                    cp_async16(&gxs[(t + PF) & 7][0][l * 4],
                               gsrc0 + (size_t)(t + PF) * 256);
                    cp_async16(&gxs[(t + PF) & 7][1][l * 4],
                               gsrc1 + (size_t)(t + PF) * 256);
                }
                asm volatile("cp.async.commit_group;");
                asm volatile("cp.async.wait_group %0;" :: "n"(PF - 1));
            }
        }
        if (doL1 && kq == 0) {
#pragma unroll
            for (int j = 0; j < 3; j++) {
                const float4 ra = *reinterpret_cast<const float4*>(&p1buf[j][0][l][0]);
                const float4 rb = *reinterpret_cast<const float4*>(&p1buf[j][1][l][0]);
                P[0][0] += ra.x; P[1][0] += ra.y; P[2][0] += ra.z; P[3][0] += ra.w;
                P[0][1] += rb.x; P[1][1] += rb.y; P[2][1] += rb.z; P[3][1] += rb.w;
            }
            {
                const float gi = P[0][0] + bi;
                const float gf = P[1][0] + bf_;
                const float gg = P[2][0] + bg;
                const float go = P[3][0] + bo;
                d0 = fsig(gf) * d0 + fsig(gi) * ftanh(gg);
                h_l0 = fsig(go) * ftanh(d0);
                ubuf[nb_][0][64 + l] = h_l0;
            }
            {
                const float gi = P[0][1] + bi;
                const float gf = P[1][1] + bf_;
                const float gg = P[2][1] + bg;
                const float go = P[3][1] + bo;
                d1 = fsig(gf) * d1 + fsig(gi) * ftanh(gg);
                h_l1 = fsig(go) * ftanh(d1);
                ubuf[nb_][1][64 + l] = h_l1;
            }
        }
        __syncthreads();   // B: h visible
    }

    // ---- FC + sigmoid on h2[T-1] ----
    if (!isL0 && kq == 0) {
        red[0][l] = h_l0 * w_fc[l];
        red[1][l] = h_l1 * w_fc[l];
    }
    __syncthreads();
    if (tid < 64) {
        const int s_ = tid >> 5, ln = tid & 31;
        float p = red[s_][ln] + red[s_][ln + 32];
#pragma unroll
        for (int o = 16; o > 0; o >>= 1)
            p += __shfl_down_sync(0xffffffffu, p, o);
        if (ln == 0) out[b0 + s_] = fsig(p + b_fc[0]);
    }
}

extern "C" void kernel_launch(void* const* d_in, const int* in_sizes, int n_in,
                              void* d_out, int out_size) {
    const float* x       = (const float*)d_in[0];
    const float* w_ih_l0 = (const float*)d_in[1];
    const float* w_hh_l0 = (const float*)d_in[2];
    const float* b_ih_l0 = (const float*)d_in[3];
    const float* b_hh_l0 = (const float*)d_in[4];
    const float* w_ih_l1 = (const float*)d_in[5];
    const float* w_hh_l1 = (const float*)d_in[6];
    const float* b_ih_l1 = (const float*)d_in[7];
    const float* b_hh_l1 = (const float*)d_in[8];
    const float* w_fc    = (const float*)d_in[9];
    const float* b_fc    = (const float*)d_in[10];
    float* out = (float*)d_out;

    float* gx0;
    cudaGetSymbolAddress((void**)&gx0, g_gx0);

    gate_gemm32<<<NM / 64, 256>>>(x, w_ih_l0, b_ih_l0, b_hh_l0, gx0);
    lstm_fused<<<NB / 2, 384>>>(gx0, w_hh_l0, w_ih_l1, w_hh_l1,
                                b_ih_l1, b_hh_l1, w_fc, b_fc, out);
}

// round 13
// speedup vs baseline: 1.7015x; 1.0400x over previous
#include <cuda_runtime.h>

#define NB 256
#define NT 1024
#define ND0 32
#define NH 64
#define NM (NB * NT)

__device__ float g_gx0[(size_t)NM * 256];   // L0 gate pre-activations [tok][gate]

using ull = unsigned long long;

__device__ __forceinline__ void ffma2(ull& d, ull a, ull b) {
    asm("fma.rn.f32x2 %0, %1, %2, %0;" : "+l"(d) : "l"(a), "l"(b));
}
__device__ __forceinline__ ull packf2(float x, float y) {
    ull r; asm("mov.b64 %0, {%1, %2};" : "=l"(r) : "f"(x), "f"(y)); return r;
}
__device__ __forceinline__ float2 unpackf2(ull v) {
    float2 f; asm("mov.b64 {%0, %1}, %2;" : "=f"(f.x), "=f"(f.y) : "l"(v)); return f;
}
__device__ __forceinline__ float ftanh(float x) {
    float y; asm("tanh.approx.f32 %0, %1;" : "=f"(y) : "f"(x)); return y;
}
__device__ __forceinline__ float fsig(float x) {
    return fmaf(0.5f, ftanh(0.5f * x), 0.5f);
}
__device__ __forceinline__ void cp_async16(void* s, const void* g) {
    unsigned sa = (unsigned)__cvta_generic_to_shared(s);
    asm volatile("cp.async.cg.shared.global [%0], [%1], 16;" :: "r"(sa), "l"(g));
}

// ===================== layer-0 gate GEMM (R11/R12 proven, unchanged) =====================
__global__ __launch_bounds__(256) void gate_gemm32(
    const float* __restrict__ X,     // [M][32]
    const float* __restrict__ w_ih,  // [256][32]
    const float* __restrict__ b_ih,
    const float* __restrict__ b_hh,
    float* __restrict__ gx)          // [M][256]
{
    __shared__ __align__(16) ull   xdup[32][80];
    __shared__ __align__(16) float wT[32][264];

    const int tid = threadIdx.x;
    const size_t tok0 = (size_t)blockIdx.x * 64;

#pragma unroll
    for (int j = 0; j < 2; j++) {
        const int idx4 = tid + j * 256;
        const int tau = idx4 >> 3, kc = idx4 & 7;
        const int ts = tau + 2 * (tau >> 3);
        const float4 v = reinterpret_cast<const float4*>(X + (tok0 + tau) * 32)[kc];
        xdup[4 * kc + 0][ts] = packf2(v.x, v.x);
        xdup[4 * kc + 1][ts] = packf2(v.y, v.y);
        xdup[4 * kc + 2][ts] = packf2(v.z, v.z);
        xdup[4 * kc + 3][ts] = packf2(v.w, v.w);
    }
    {
        const float4* wr = reinterpret_cast<const float4*>(w_ih + tid * 32);
#pragma unroll
        for (int c = 0; c < 8; c++) {
            const float4 v = wr[c];
            wT[4 * c + 0][tid] = v.x;
            wT[4 * c + 1][tid] = v.y;
            wT[4 * c + 2][tid] = v.z;
            wT[4 * c + 3][tid] = v.w;
        }
    }

    const int tokg = tid & 7;
    const int gg   = tid >> 3;
    const int t0s = tokg * 10;
    const int t0  = tokg * 8;
    const int g0  = gg * 8;

    ull acc[8][4];
#pragma unroll
    for (int p = 0; p < 4; p++) {
        const ull bp = packf2(b_ih[g0 + 2 * p]     + b_hh[g0 + 2 * p],
                              b_ih[g0 + 2 * p + 1] + b_hh[g0 + 2 * p + 1]);
#pragma unroll
        for (int tk = 0; tk < 8; tk++) acc[tk][p] = bp;
    }

    __syncthreads();

#pragma unroll 4
    for (int k = 0; k < 32; k++) {
        const ulonglong2 wa = *reinterpret_cast<const ulonglong2*>(&wT[k][g0]);
        const ulonglong2 wb = *reinterpret_cast<const ulonglong2*>(&wT[k][g0 + 4]);
        const ull w01[4] = {wa.x, wa.y, wb.x, wb.y};
        const ulonglong2* xr = reinterpret_cast<const ulonglong2*>(&xdup[k][t0s]);
#pragma unroll
        for (int h = 0; h < 4; h++) {
            const ulonglong2 xv = xr[h];
#pragma unroll
            for (int p = 0; p < 4; p++) {
                ffma2(acc[2 * h][p],     xv.x, w01[p]);
                ffma2(acc[2 * h + 1][p], xv.y, w01[p]);
            }
        }
    }

#pragma unroll
    for (int tk = 0; tk < 8; tk++) {
        ulonglong2* dst =
            reinterpret_cast<ulonglong2*>(gx + (tok0 + t0 + tk) * 256 + g0);
        dst[0] = make_ulonglong2(acc[tk][0], acc[tk][1]);
        dst[1] = make_ulonglong2(acc[tk][2], acc[tk][3]);
    }
}

// ===================== fused L0 + L1: broadcast u + DE-SPILLED registers ==========
// R12 structure, but the dot runs as two sample-sequential passes with A[4]
// accumulators (not A[4][2]) and partials exported to smem IMMEDIATELY —
// no thread holds P[4][2] across the barrier. Non-weight regs ~25 -> total
// ~155 < cap 170: the 128-reg weight arrays stay resident (no local spills).
__global__ __launch_bounds__(384) void lstm_fused(
    const float* __restrict__ gx0,    // [B][T][256] (with L0 biases)
    const float* __restrict__ w_hh0,  // [256][64]
    const float* __restrict__ w_ih1,  // [256][64]
    const float* __restrict__ w_hh1,  // [256][64]
    const float* __restrict__ b_ih1,  // [256]
    const float* __restrict__ b_hh1,  // [256]
    const float* __restrict__ w_fc,   // [64]
    const float* __restrict__ b_fc,   // [1]
    float* __restrict__ out)          // [B]
{
    constexpr int PF = 7;

    __shared__ __align__(16) float ubuf[2][2][128];    // [buf][sample][h1|h2]
    __shared__ __align__(16) float gxs[8][2][256];     // gx0 ring
    __shared__ __align__(16) float p0buf[2][2][64][4]; // [q][s][l][gate]
    __shared__ __align__(16) float p1buf[4][2][64][4]; // [kq][s][l][gate]
    __shared__ float red[2][NH];

    const int tid  = threadIdx.x;
    const int b0   = blockIdx.x * 2;
    const bool isL0 = (tid < 128);

    for (int i = tid; i < 2 * 2 * 128; i += 384) (&ubuf[0][0][0])[i] = 0.0f;

    const int q  = (tid >> 6) & 1;     // L0 k-half    (warp-constant)
    const int rt = tid - 128;
    const int kq = rt >> 6;            // L1 k-quarter (warp-constant)
    const int l  = tid & 63;

    // ---- weights: 4 gate rows x 32 floats (my k-slice) -> 128 regs ----
    ull w[4][16];
    float bi = 0.f, bf_ = 0.f, bg = 0.f, bo = 0.f;
    if (isL0) {
#pragma unroll
        for (int g4 = 0; g4 < 4; g4++) {
            const int row = 64 * g4 + l;
#pragma unroll
            for (int i = 0; i < 16; i++) {
                const int k = 32 * q + 2 * i;
                w[g4][i] = packf2(w_hh0[row * NH + k], w_hh0[row * NH + k + 1]);
            }
        }
    } else {
#pragma unroll
        for (int g4 = 0; g4 < 4; g4++) {
            const int row = 64 * g4 + l;
#pragma unroll
            for (int i = 0; i < 16; i++) {
                const int kk = 32 * kq + 2 * i;
                const float a = (kk < 64) ? w_ih1[row * 64 + kk]
                                          : w_hh1[row * 64 + kk - 64];
                const float b = (kk < 64) ? w_ih1[row * 64 + kk + 1]
                                          : w_hh1[row * 64 + kk - 63];
                w[g4][i] = packf2(a, b);
            }
        }
        if (kq == 0) {
            bi  = b_ih1[l]       + b_hh1[l];
            bf_ = b_ih1[64 + l]  + b_hh1[64 + l];
            bg  = b_ih1[128 + l] + b_hh1[128 + l];
            bo  = b_ih1[192 + l] + b_hh1[192 + l];
        }
    }

    // gx ring loaders: L0 q==1 threads (tid 64..127)
    const bool isload = isL0 && (q == 1);
    const float* gsrc0 = gx0 + ((size_t)(b0 + 0) * NT) * 256 + l * 4;
    const float* gsrc1 = gx0 + ((size_t)(b0 + 1) * NT) * 256 + l * 4;
    if (isload) {
#pragma unroll
        for (int p = 0; p < PF; p++) {
            cp_async16(&gxs[p][0][l * 4], gsrc0 + (size_t)p * 256);
            cp_async16(&gxs[p][1][l * 4], gsrc1 + (size_t)p * 256);
            asm volatile("cp.async.commit_group;");
        }
        asm volatile("cp.async.wait_group %0;" :: "n"(PF - 1));
    }
    __syncthreads();

    float c0 = 0.f, c1 = 0.f;          // L0 cell states   (q==0)
    float d0 = 0.f, d1 = 0.f;          // L1 cell states   (kq==0)
    float h_l0 = 0.f, h_l1 = 0.f;      // L1 last hidden

#pragma unroll 1
    for (int t = 0; t <= NT; t++) {
        const int cb = t & 1, nb_ = cb ^ 1;

        const bool doL0 = isL0 && (t < NT);
        const bool doL1 = !isL0 && (t >= 1);

        if (doL0 || doL1) {
            const int base = isL0 ? 32 * q : 32 * kq;
            // sample-sequential passes: A[4] only, partials exported at once
#pragma unroll
            for (int s = 0; s < 2; s++) {
                const ulonglong2* u =
                    reinterpret_cast<const ulonglong2*>(&ubuf[cb][s][base]);
                ull A0 = 0, A1 = 0, A2 = 0, A3 = 0;
#pragma unroll
                for (int i = 0; i < 8; i++) {
                    const ulonglong2 v = u[i];     // warp-uniform broadcast
                    ffma2(A0, v.x, w[0][2 * i]); ffma2(A0, v.y, w[0][2 * i + 1]);
                    ffma2(A1, v.x, w[1][2 * i]); ffma2(A1, v.y, w[1][2 * i + 1]);
                    ffma2(A2, v.x, w[2][2 * i]); ffma2(A2, v.y, w[2][2 * i + 1]);
                    ffma2(A3, v.x, w[3][2 * i]); ffma2(A3, v.y, w[3][2 * i + 1]);
                }
                const float2 f0 = unpackf2(A0);
                const float2 f1 = unpackf2(A1);
                const float2 f2 = unpackf2(A2);
                const float2 f3 = unpackf2(A3);
                const float4 p4 = make_float4(f0.x + f0.y, f1.x + f1.y,
                                              f2.x + f2.y, f3.x + f3.y);
                if (isL0) *reinterpret_cast<float4*>(&p0buf[q][s][l][0]) = p4;
                else      *reinterpret_cast<float4*>(&p1buf[kq][s][l][0]) = p4;
            }
        }
        __syncthreads();   // A: partials visible

        if (doL0) {
            if (q == 0) {
                const float* gb0 = &gxs[t & 7][0][0];
                const float* gb1 = &gxs[t & 7][1][0];
                {
                    const float4 a = *reinterpret_cast<const float4*>(&p0buf[0][0][l][0]);
                    const float4 b = *reinterpret_cast<const float4*>(&p0buf[1][0][l][0]);
                    const float gi = a.x + b.x + gb0[l];
                    const float gf = a.y + b.y + gb0[64 + l];
                    const float gg = a.z + b.z + gb0[128 + l];
                    const float go = a.w + b.w + gb0[192 + l];
                    c0 = fsig(gf) * c0 + fsig(gi) * ftanh(gg);
                    ubuf[nb_][0][l] = fsig(go) * ftanh(c0);
                }
                {
                    const float4 a = *reinterpret_cast<const float4*>(&p0buf[0][1][l][0]);
                    const float4 b = *reinterpret_cast<const float4*>(&p0buf[1][1][l][0]);
                    const float gi = a.x + b.x + gb1[l];
                    const float gf = a.y + b.y + gb1[64 + l];
                    const float gg = a.z + b.z + gb1[128 + l];
                    const float go = a.w + b.w + gb1[192 + l];
                    c1 = fsig(gf) * c1 + fsig(gi) * ftanh(gg);
                    ubuf[nb_][1][l] = fsig(go) * ftanh(c1);
                }
            } else {
                if (t + PF < NT) {
                    cp_async16(&gxs[(t + PF) & 7][0][l * 4],
                               gsrc0 + (size_t)(t + PF) * 256);
                    cp_async16(&gxs[(t + PF) & 7][1][l * 4],
                               gsrc1 + (size_t)(t + PF) * 256);
                }
                asm volatile("cp.async.commit_group;");
                asm volatile("cp.async.wait_group %0;" :: "n"(PF - 1));
            }
        }
        if (doL1 && kq == 0) {
            {
                const float4 a0 = *reinterpret_cast<const float4*>(&p1buf[0][0][l][0]);
                const float4 a1 = *reinterpret_cast<const float4*>(&p1buf[1][0][l][0]);
                const float4 a2 = *reinterpret_cast<const float4*>(&p1buf[2][0][l][0]);
                const float4 a3 = *reinterpret_cast<const float4*>(&p1buf[3][0][l][0]);
                const float gi = ((a0.x + a1.x) + a2.x) + a3.x + bi;
                const float gf = ((a0.y + a1.y) + a2.y) + a3.y + bf_;
                const float gg = ((a0.z + a1.z) + a2.z) + a3.z + bg;
                const float go = ((a0.w + a1.w) + a2.w) + a3.w + bo;
                d0 = fsig(gf) * d0 + fsig(gi) * ftanh(gg);
                h_l0 = fsig(go) * ftanh(d0);
                ubuf[nb_][0][64 + l] = h_l0;
            }
            {
                const float4 a0 = *reinterpret_cast<const float4*>(&p1buf[0][1][l][0]);
                const float4 a1 = *reinterpret_cast<const float4*>(&p1buf[1][1][l][0]);
                const float4 a2 = *reinterpret_cast<const float4*>(&p1buf[2][1][l][0]);
                const float4 a3 = *reinterpret_cast<const float4*>(&p1buf[3][1][l][0]);
                const float gi = ((a0.x + a1.x) + a2.x) + a3.x + bi;
                const float gf = ((a0.y + a1.y) + a2.y) + a3.y + bf_;
                const float gg = ((a0.z + a1.z) + a2.z) + a3.z + bg;
                const float go = ((a0.w + a1.w) + a2.w) + a3.w + bo;
                d1 = fsig(gf) * d1 + fsig(gi) * ftanh(gg);
                h_l1 = fsig(go) * ftanh(d1);
                ubuf[nb_][1][64 + l] = h_l1;
            }
        }
        __syncthreads();   // B: h visible
    }

    // ---- FC + sigmoid on h2[T-1] ----
    if (!isL0 && kq == 0) {
        red[0][l] = h_l0 * w_fc[l];
        red[1][l] = h_l1 * w_fc[l];
    }
    __syncthreads();
    if (tid < 64) {
        const int s_ = tid >> 5, ln = tid & 31;
        float p = red[s_][ln] + red[s_][ln + 32];
#pragma unroll
        for (int o = 16; o > 0; o >>= 1)
            p += __shfl_down_sync(0xffffffffu, p, o);
        if (ln == 0) out[b0 + s_] = fsig(p + b_fc[0]);
    }
}

extern "C" void kernel_launch(void* const* d_in, const int* in_sizes, int n_in,
                              void* d_out, int out_size) {
    const float* x       = (const float*)d_in[0];
    const float* w_ih_l0 = (const float*)d_in[1];
    const float* w_hh_l0 = (const float*)d_in[2];
    const float* b_ih_l0 = (const float*)d_in[3];
    const float* b_hh_l0 = (const float*)d_in[4];
    const float* w_ih_l1 = (const float*)d_in[5];
    const float* w_hh_l1 = (const float*)d_in[6];
    const float* b_ih_l1 = (const float*)d_in[7];
    const float* b_hh_l1 = (const float*)d_in[8];
    const float* w_fc    = (const float*)d_in[9];
    const float* b_fc    = (const float*)d_in[10];
    float* out = (float*)d_out;

    float* gx0;
    cudaGetSymbolAddress((void**)&gx0, g_gx0);

    gate_gemm32<<<NM / 64, 256>>>(x, w_ih_l0, b_ih_l0, b_hh_l0, gx0);
    lstm_fused<<<NB / 2, 384>>>(gx0, w_hh_l0, w_ih_l1, w_hh_l1,
                                b_ih_l1, b_hh_l1, w_fc, b_fc, out);
}